// round 2
// baseline (speedup 1.0000x reference)
#include <cuda_runtime.h>
#include <cuda_bf16.h>
#include <cstdint>

// Problem constants (fixed by the reference)
#define N_NODES 100000
#define N_EDGES 1600000
#define IN_C 64
#define HID 128
#define OUT_C 64

// Scratch (no allocations allowed -> __device__ globals)
__device__ float g_h2[(size_t)N_NODES * OUT_C];   // post-W2 node features [N,64]
__device__ float g_deg[N_NODES];
__device__ float g_dinv[N_NODES];
__device__ int   g_is64;                          // edge_index dtype flag

// ---------------------------------------------------------------------------
// Edge-index dtype detection.
// int64 values in [0,1e5) have all-zero odd 32-bit words (little-endian).
// int32 edge data has random indices in the odd words -> essentially never
// 128 consecutive zeros. Deterministic for fixed input.
// ---------------------------------------------------------------------------
__global__ void k_detect(const int* __restrict__ ei_words) {
    int nz = 0;
    #pragma unroll 8
    for (int i = 0; i < 128; ++i) nz += (ei_words[2 * i + 1] != 0);
    g_is64 = (nz == 0) ? 1 : 0;
}

__device__ __forceinline__ int edge_at(const void* ei, long long i, int is64) {
    if (is64) return (int)((const long long*)ei)[i];
    return ((const int*)ei)[i];
}

// ---------------------------------------------------------------------------
// Degree kernels
// ---------------------------------------------------------------------------
__global__ void k_deg_init() {
    int i = blockIdx.x * blockDim.x + threadIdx.x;
    if (i < N_NODES) g_deg[i] = 1.0f;   // self-loop
}

__global__ void k_deg_count(const void* __restrict__ ei) {
    int is64 = g_is64;
    int stride = gridDim.x * blockDim.x;
    for (int i = blockIdx.x * blockDim.x + threadIdx.x; i < N_EDGES; i += stride) {
        int d = edge_at(ei, (long long)N_EDGES + i, is64);   // dst row
        atomicAdd(&g_deg[d], 1.0f);
    }
}

__global__ void k_dinv() {
    int i = blockIdx.x * blockDim.x + threadIdx.x;
    if (i < N_NODES) g_dinv[i] = rsqrtf(g_deg[i]);
}

// ---------------------------------------------------------------------------
// Fused MLP: h2 = relu(X@W1 + b1) @ W2, epilogue: out = h2*dinv^2 + b2
// One warp per node row. Weights staged in dynamic smem, persistent blocks.
// ---------------------------------------------------------------------------
__global__ __launch_bounds__(256) void k_mlp(
    const float* __restrict__ X,
    const float* __restrict__ W1, const float* __restrict__ b1,
    const float* __restrict__ W2, const float* __restrict__ b2,
    float* __restrict__ out)
{
    extern __shared__ float smem[];
    float* sW1  = smem;                 // 64*128
    float* sW2  = sW1 + IN_C * HID;     // 128*64
    float* sB1  = sW2 + HID * OUT_C;    // 128
    float* sB2  = sB1 + HID;            // 64
    float* sHid = sB2 + OUT_C;          // nwarps*128

    int tid = threadIdx.x;
    for (int i = tid; i < IN_C * HID; i += blockDim.x) sW1[i] = W1[i];
    for (int i = tid; i < HID * OUT_C; i += blockDim.x) sW2[i] = W2[i];
    if (tid < HID)   sB1[tid] = b1[tid];
    if (tid < OUT_C) sB2[tid] = b2[tid];
    __syncthreads();

    int warp = tid >> 5, lane = tid & 31;
    int nwarps = blockDim.x >> 5;
    int gw = blockIdx.x * nwarps + warp;
    int gstride = gridDim.x * nwarps;
    float* hid = sHid + warp * HID;

    for (int node = gw; node < N_NODES; node += gstride) {
        // load x row: 64 floats, 2 per lane
        float2 xv = ((const float2*)X)[(size_t)node * 32 + lane];

        // stage 1: hid[128] = relu(x @ W1 + b1); lane owns cols lane+32j
        float a0 = sB1[lane], a1 = sB1[lane + 32], a2 = sB1[lane + 64], a3 = sB1[lane + 96];
        #pragma unroll
        for (int k = 0; k < IN_C; ++k) {
            float xk = __shfl_sync(0xffffffffu, (k & 1) ? xv.y : xv.x, k >> 1);
            const float* w = sW1 + k * HID + lane;
            a0 = fmaf(xk, w[0],  a0);
            a1 = fmaf(xk, w[32], a1);
            a2 = fmaf(xk, w[64], a2);
            a3 = fmaf(xk, w[96], a3);
        }
        hid[lane]      = fmaxf(a0, 0.0f);
        hid[lane + 32] = fmaxf(a1, 0.0f);
        hid[lane + 64] = fmaxf(a2, 0.0f);
        hid[lane + 96] = fmaxf(a3, 0.0f);
        __syncwarp();

        // stage 2: h2[64] = hid @ W2; lane owns cols 2*lane, 2*lane+1
        float o0 = 0.0f, o1 = 0.0f;
        #pragma unroll 16
        for (int h = 0; h < HID; ++h) {
            float hv = hid[h];
            float2 w = ((const float2*)sW2)[h * 32 + lane];
            o0 = fmaf(hv, w.x, o0);
            o1 = fmaf(hv, w.y, o1);
        }
        ((float2*)g_h2)[(size_t)node * 32 + lane] = make_float2(o0, o1);

        // epilogue: self-loop message + bias initializes out
        float di = g_dinv[node];
        float ws = di * di;
        float2 ob = make_float2(fmaf(o0, ws, sB2[2 * lane]),
                                fmaf(o1, ws, sB2[2 * lane + 1]));
        ((float2*)out)[(size_t)node * 32 + lane] = ob;
        __syncwarp();   // hid reuse next iteration
    }
}

// ---------------------------------------------------------------------------
// Edge scatter: out[dst] += h2[src] * dinv[src]*dinv[dst]
// Warp processes 32 edges per batch: coalesced index loads, then broadcast
// each edge's (src,dst,w) via shfl while all 32 lanes do the coalesced
// 256B row gather + red.global.add.v2. N_EDGES % 32 == 0, no tail.
// ---------------------------------------------------------------------------
__global__ __launch_bounds__(256) void k_scatter(
    const void* __restrict__ ei, float* __restrict__ out)
{
    int is64 = g_is64;
    int lane = threadIdx.x & 31;
    int warp = (blockIdx.x * blockDim.x + threadIdx.x) >> 5;
    int nw = (gridDim.x * blockDim.x) >> 5;

    for (int base = warp * 32; base < N_EDGES; base += nw * 32) {
        long long e = base + lane;
        int s = edge_at(ei, e, is64);
        int d = edge_at(ei, e + N_EDGES, is64);
        float w = g_dinv[s] * g_dinv[d];

        #pragma unroll 4
        for (int j = 0; j < 32; ++j) {
            int   sj = __shfl_sync(0xffffffffu, s, j);
            int   dj = __shfl_sync(0xffffffffu, d, j);
            float wj = __shfl_sync(0xffffffffu, w, j);
            float2 v = ((const float2*)g_h2)[(size_t)sj * 32 + lane];
            float* p = out + (size_t)dj * OUT_C + 2 * lane;
            asm volatile("red.global.add.v2.f32 [%0], {%1, %2};"
                         :: "l"(p), "f"(v.x * wj), "f"(v.y * wj) : "memory");
        }
    }
}

// ---------------------------------------------------------------------------
// Launch
// Inputs (metadata order): node_features f32[N*64], edge_index [2*E] (i32 or
// i64, detected at runtime), W1 f32[64*128], b1 f32[128], W2 f32[128*64],
// b2 f32[64]. Output: f32[N*64].
// ---------------------------------------------------------------------------
extern "C" void kernel_launch(void* const* d_in, const int* in_sizes, int n_in,
                              void* d_out, int out_size)
{
    const float* X  = (const float*)d_in[0];
    const void*  EI = d_in[1];
    const float* W1 = (const float*)d_in[2];
    const float* b1 = (const float*)d_in[3];
    const float* W2 = (const float*)d_in[4];
    const float* b2 = (const float*)d_in[5];
    float* out = (float*)d_out;

    // dtype detection (1 thread, ~free)
    k_detect<<<1, 1>>>((const int*)EI);

    // degrees
    k_deg_init<<<(N_NODES + 255) / 256, 256>>>();
    k_deg_count<<<1184, 256>>>(EI);
    k_dinv<<<(N_NODES + 255) / 256, 256>>>();

    // fused MLP with dynamic smem (weights + per-warp hid staging)
    const int MLP_THREADS = 256;
    const int MLP_WARPS = MLP_THREADS / 32;
    size_t smem = (size_t)(IN_C * HID + HID * OUT_C + HID + OUT_C + MLP_WARPS * HID) * sizeof(float);
    cudaFuncSetAttribute(k_mlp, cudaFuncAttributeMaxDynamicSharedMemorySize, (int)smem);
    k_mlp<<<444, MLP_THREADS, smem>>>(X, W1, b1, W2, b2, out);

    // edge scatter
    k_scatter<<<1184, 256>>>(EI, out);
}

// round 3
// speedup vs baseline: 1.5048x; 1.5048x over previous
#include <cuda_runtime.h>
#include <cuda_bf16.h>
#include <cstdint>

#define N_NODES 100000
#define N_EDGES 1600000
#define IN_C 64
#define HID 128
#define OUT_C 64
#define NB1 196              // ceil(N_NODES/512) scan blocks
#define N_TILES 1563         // ceil(N_NODES/64)

typedef unsigned long long u64;

// Scratch (__device__ globals; no allocs allowed)
__device__ float g_h2[(size_t)N_NODES * OUT_C];
__device__ float g_deg[N_NODES];
__device__ float g_dinv[N_NODES];
__device__ int   g_off[N_NODES];
__device__ int   g_cursor[N_NODES];
__device__ int   g_bsum[NB1];
__device__ int   g_esrc[N_EDGES];
__device__ int   g_is64;

// ---------------------------------------------------------------------------
// f32x2 packed helpers (Blackwell FFMA2 path)
// ---------------------------------------------------------------------------
__device__ __forceinline__ u64 pack2(float lo, float hi) {
    u64 r; asm("mov.b64 %0, {%1, %2};" : "=l"(r) : "f"(lo), "f"(hi)); return r;
}
__device__ __forceinline__ u64 dup2(float v) { return pack2(v, v); }
__device__ __forceinline__ void unpack2(u64 p, float& lo, float& hi) {
    asm("mov.b64 {%0, %1}, %2;" : "=f"(lo), "=f"(hi) : "l"(p));
}
__device__ __forceinline__ u64 ffma2(u64 a, u64 b, u64 c) {
    u64 d; asm("fma.rn.f32x2 %0, %1, %2, %3;" : "=l"(d) : "l"(a), "l"(b), "l"(c)); return d;
}

// ---------------------------------------------------------------------------
// Edge-index dtype detection (int64 values <1e5 -> all odd 32-bit words zero)
// ---------------------------------------------------------------------------
__global__ void k_detect(const int* __restrict__ w) {
    int nz = 0;
    #pragma unroll 8
    for (int i = 0; i < 128; ++i) nz += (w[2 * i + 1] != 0);
    g_is64 = (nz == 0) ? 1 : 0;
}
__device__ __forceinline__ int edge_at(const void* ei, long long i, int is64) {
    return is64 ? (int)((const long long*)ei)[i] : ((const int*)ei)[i];
}

// ---------------------------------------------------------------------------
// Degree
// ---------------------------------------------------------------------------
__global__ void k_deg_init() {
    int i = blockIdx.x * blockDim.x + threadIdx.x;
    if (i < N_NODES) g_deg[i] = 1.0f;          // self-loop
}
__global__ void k_deg_count(const void* __restrict__ ei) {
    int is64 = g_is64;
    int stride = gridDim.x * blockDim.x;
    for (int i = blockIdx.x * blockDim.x + threadIdx.x; i < N_EDGES; i += stride)
        atomicAdd(&g_deg[edge_at(ei, (long long)N_EDGES + i, is64)], 1.0f);
}
__global__ void k_dinv() {
    int i = blockIdx.x * blockDim.x + threadIdx.x;
    if (i < N_NODES) g_dinv[i] = rsqrtf(g_deg[i]);
}

// ---------------------------------------------------------------------------
// Fused MLP: g_h2 = relu(X@W1 + b1) @ W2   (64-node tiles, FFMA2-packed)
// ---------------------------------------------------------------------------
__global__ __launch_bounds__(256, 1) void k_mlp(
    const float* __restrict__ X,
    const float* __restrict__ W1, const float* __restrict__ b1,
    const float* __restrict__ W2)
{
    extern __shared__ float smem[];
    float* sW1 = smem;                 // 64*128
    float* sW2 = sW1 + IN_C * HID;     // 128*64
    float* sB1 = sW2 + HID * OUT_C;    // 128
    float* sX  = sB1 + HID;            // 64*64
    float* sH  = sX + 64 * IN_C;       // 64*132 (padded rows)

    int tid = threadIdx.x;
    for (int i = tid; i < IN_C * HID; i += 256) { sW1[i] = W1[i]; sW2[i] = W2[i]; }
    if (tid < HID) sB1[tid] = b1[tid];
    __syncthreads();

    int c2 = tid & 15;        // column group
    int ng = tid >> 4;        // node group: nodes ng*4 .. ng*4+3

    for (int tile = blockIdx.x; tile < N_TILES; tile += gridDim.x) {
        int nbase = tile * 64;
        __syncthreads();      // protect sX/sH reuse

        // load X tile [64 x 64] coalesced (float4), zero-pad tail
        for (int q = tid; q < 1024; q += 256) {
            int n = q >> 4, t = q & 15;
            float4 v = make_float4(0.f, 0.f, 0.f, 0.f);
            if (nbase + n < N_NODES)
                v = ((const float4*)X)[(size_t)(nbase + n) * 16 + t];
            *(float4*)&sX[n * IN_C + t * 4] = v;
        }
        __syncthreads();

        // ---- stage 1: H[64x128] = relu(X @ W1 + b1)
        // thread: 4 nodes (ng*4+i) x 8 cols (8*c2 + 2p..2p+1), 4 col-pairs
        {
            u64 acc[4][4];
            #pragma unroll
            for (int p = 0; p < 4; ++p) {
                u64 bp = *(const u64*)&sB1[8 * c2 + 2 * p];
                #pragma unroll
                for (int i = 0; i < 4; ++i) acc[i][p] = bp;
            }
            #pragma unroll 4
            for (int k = 0; k < IN_C; ++k) {
                u64 w[4];
                #pragma unroll
                for (int p = 0; p < 4; ++p)
                    w[p] = *(const u64*)&sW1[k * HID + 8 * c2 + 2 * p];
                #pragma unroll
                for (int i = 0; i < 4; ++i) {
                    u64 xd = dup2(sX[(ng * 4 + i) * IN_C + k]);
                    #pragma unroll
                    for (int p = 0; p < 4; ++p)
                        acc[i][p] = ffma2(xd, w[p], acc[i][p]);
                }
            }
            #pragma unroll
            for (int i = 0; i < 4; ++i)
                #pragma unroll
                for (int p = 0; p < 4; ++p) {
                    float lo, hi; unpack2(acc[i][p], lo, hi);
                    lo = fmaxf(lo, 0.f); hi = fmaxf(hi, 0.f);
                    *(u64*)&sH[(ng * 4 + i) * 132 + 8 * c2 + 2 * p] = pack2(lo, hi);
                }
        }
        __syncthreads();

        // ---- stage 2: h2[64x64] = H @ W2
        // thread: 4 nodes x 4 cols (4*c2 + 2p..2p+1), 2 col-pairs
        {
            u64 o[4][2];
            #pragma unroll
            for (int i = 0; i < 4; ++i) { o[i][0] = 0ull; o[i][1] = 0ull; }
            #pragma unroll 4
            for (int k = 0; k < HID; ++k) {
                u64 w0 = *(const u64*)&sW2[k * OUT_C + 4 * c2];
                u64 w1 = *(const u64*)&sW2[k * OUT_C + 4 * c2 + 2];
                #pragma unroll
                for (int i = 0; i < 4; ++i) {
                    u64 hd = dup2(sH[(ng * 4 + i) * 132 + k]);
                    o[i][0] = ffma2(hd, w0, o[i][0]);
                    o[i][1] = ffma2(hd, w1, o[i][1]);
                }
            }
            #pragma unroll
            for (int i = 0; i < 4; ++i) {
                int n = nbase + ng * 4 + i;
                if (n < N_NODES) {
                    float4 hv;
                    unpack2(o[i][0], hv.x, hv.y);
                    unpack2(o[i][1], hv.z, hv.w);
                    ((float4*)g_h2)[(size_t)n * 16 + c2] = hv;
                }
            }
        }
    }
}

// ---------------------------------------------------------------------------
// Scan of per-node in-edge counts -> g_off (CSR row offsets)
// ---------------------------------------------------------------------------
__global__ void k_scan1() {
    __shared__ int sh[512];
    int tid = threadIdx.x;
    int i = blockIdx.x * 512 + tid;
    int v = (i < N_NODES) ? ((int)g_deg[i] - 1) : 0;
    sh[tid] = v;
    __syncthreads();
    for (int off = 1; off < 512; off <<= 1) {
        int t = (tid >= off) ? sh[tid - off] : 0;
        __syncthreads();
        sh[tid] += t;
        __syncthreads();
    }
    if (i < N_NODES) { g_off[i] = sh[tid] - v; g_cursor[i] = 0; }
    if (tid == 511) g_bsum[blockIdx.x] = sh[511];
}
__global__ void k_scan2() {
    __shared__ int sh[256];
    int tid = threadIdx.x;
    int v = (tid < NB1) ? g_bsum[tid] : 0;
    sh[tid] = v;
    __syncthreads();
    for (int off = 1; off < 256; off <<= 1) {
        int t = (tid >= off) ? sh[tid - off] : 0;
        __syncthreads();
        sh[tid] += t;
        __syncthreads();
    }
    if (tid < NB1) g_bsum[tid] = sh[tid] - v;   // exclusive
}
__global__ void k_scan3() {
    int i = blockIdx.x * blockDim.x + threadIdx.x;
    if (i < N_NODES) g_off[i] += g_bsum[i >> 9];
}

// ---------------------------------------------------------------------------
// Bin edges by dst: g_esrc[g_off[d] + cursor++] = s
// ---------------------------------------------------------------------------
__global__ void k_bin(const void* __restrict__ ei) {
    int is64 = g_is64;
    int stride = gridDim.x * blockDim.x;
    for (int e = blockIdx.x * blockDim.x + threadIdx.x; e < N_EDGES; e += stride) {
        int s = edge_at(ei, e, is64);
        int d = edge_at(ei, (long long)N_EDGES + e, is64);
        int pos = atomicAdd(&g_cursor[d], 1);
        g_esrc[g_off[d] + pos] = s;
    }
}

// ---------------------------------------------------------------------------
// Gather: one warp per dst node, register accumulation, single write of out.
// out[d] = b2 + dinv[d]*(dinv[d]*h2[d] + sum_s dinv[s]*h2[s])
// ---------------------------------------------------------------------------
__global__ __launch_bounds__(256) void k_gather(
    const float* __restrict__ b2, float* __restrict__ out)
{
    int lane = threadIdx.x & 31;
    int d = (blockIdx.x * blockDim.x + threadIdx.x) >> 5;
    if (d >= N_NODES) return;

    int cnt = (int)g_deg[d] - 1;
    int base = g_off[d];
    float a0 = 0.f, a1 = 0.f;

    for (int c = 0; c < cnt; c += 32) {
        int m = cnt - c; if (m > 32) m = 32;
        int s = 0; float wt = 0.f;
        if (lane < m) { s = g_esrc[base + c + lane]; wt = g_dinv[s]; }
        for (int j = 0; j < m; ++j) {
            int   sj = __shfl_sync(0xffffffffu, s, j);
            float wj = __shfl_sync(0xffffffffu, wt, j);
            float2 v = ((const float2*)g_h2)[(size_t)sj * 32 + lane];
            a0 = fmaf(v.x, wj, a0);
            a1 = fmaf(v.y, wj, a1);
        }
    }
    float di = g_dinv[d];
    float2 hs = ((const float2*)g_h2)[(size_t)d * 32 + lane];
    float2 bb = ((const float2*)b2)[lane];
    float2 o;
    o.x = bb.x + di * fmaf(di, hs.x, a0);
    o.y = bb.y + di * fmaf(di, hs.y, a1);
    ((float2*)out)[(size_t)d * 32 + lane] = o;
}

// ---------------------------------------------------------------------------
// Launch. Inputs: X f32[N*64], edge_index (i32/i64)[2E], W1, b1, W2, b2.
// ---------------------------------------------------------------------------
extern "C" void kernel_launch(void* const* d_in, const int* in_sizes, int n_in,
                              void* d_out, int out_size)
{
    const float* X  = (const float*)d_in[0];
    const void*  EI = d_in[1];
    const float* W1 = (const float*)d_in[2];
    const float* b1 = (const float*)d_in[3];
    const float* W2 = (const float*)d_in[4];
    const float* b2 = (const float*)d_in[5];
    float* out = (float*)d_out;

    size_t smem = (size_t)(IN_C * HID + HID * OUT_C + HID + 64 * IN_C + 64 * 132) * sizeof(float);
    cudaFuncSetAttribute(k_mlp, cudaFuncAttributeMaxDynamicSharedMemorySize, (int)smem);

    k_detect<<<1, 1>>>((const int*)EI);                       // 0
    k_deg_init<<<(N_NODES + 255) / 256, 256>>>();             // 1
    k_deg_count<<<1184, 256>>>(EI);                           // 2
    k_mlp<<<148, 256, smem>>>(X, W1, b1, W2);                 // 3  <- ncu aim
    k_dinv<<<(N_NODES + 255) / 256, 256>>>();                 // 4
    k_scan1<<<NB1, 512>>>();                                  // 5
    k_scan2<<<1, 256>>>();                                    // 6
    k_scan3<<<(N_NODES + 255) / 256, 256>>>();                // 7
    k_bin<<<1184, 256>>>(EI);                                 // 8
    k_gather<<<(N_NODES * 32 + 255) / 256, 256>>>(b2, out);   // 9
}

// round 4
// speedup vs baseline: 1.6023x; 1.0648x over previous
#include <cuda_runtime.h>
#include <cuda_bf16.h>
#include <cstdint>

#define N_NODES 100000
#define N_EDGES 1600000
#define IN_C 64
#define HID 128
#define OUT_C 64
#define NB1 196              // ceil(N_NODES/512)
#define N_TILES 1563         // ceil(N_NODES/64)

typedef unsigned long long u64;

// Scratch (__device__ globals; no allocs allowed)
__device__ float g_h2[(size_t)N_NODES * OUT_C];   // dinv-scaled post-W2 features
__device__ float g_deg[N_NODES];
__device__ float g_dinv[N_NODES];
__device__ int   g_off[N_NODES];
__device__ int   g_cursor[N_NODES];
__device__ int   g_bsum[NB1];
__device__ int   g_esrc[N_EDGES];
__device__ int   g_is64;

// ---------------------------------------------------------------------------
// f32x2 helpers
// ---------------------------------------------------------------------------
__device__ __forceinline__ u64 pack2(float lo, float hi) {
    u64 r; asm("mov.b64 %0, {%1, %2};" : "=l"(r) : "f"(lo), "f"(hi)); return r;
}
__device__ __forceinline__ void unpack2(u64 p, float& lo, float& hi) {
    asm("mov.b64 {%0, %1}, %2;" : "=f"(lo), "=f"(hi) : "l"(p));
}
__device__ __forceinline__ u64 ffma2(u64 a, u64 b, u64 c) {
    u64 d; asm("fma.rn.f32x2 %0, %1, %2, %3;" : "=l"(d) : "l"(a), "l"(b), "l"(c)); return d;
}

// ---------------------------------------------------------------------------
// init: deg=1 (self-loop) + edge dtype detection (block 0 thread 0)
// ---------------------------------------------------------------------------
__global__ void k_init(const int* __restrict__ w) {
    int i = blockIdx.x * blockDim.x + threadIdx.x;
    if (i < N_NODES) g_deg[i] = 1.0f;
    if (i == 0) {
        int nz = 0;
        #pragma unroll 8
        for (int j = 0; j < 128; ++j) nz += (w[2 * j + 1] != 0);
        g_is64 = (nz == 0) ? 1 : 0;
    }
}
__device__ __forceinline__ int edge_at(const void* ei, long long i, int is64) {
    return is64 ? (int)((const long long*)ei)[i] : ((const int*)ei)[i];
}

__global__ void k_deg_count(const void* __restrict__ ei) {
    int is64 = g_is64;
    int stride = gridDim.x * blockDim.x;
    for (int i = blockIdx.x * blockDim.x + threadIdx.x; i < N_EDGES; i += stride)
        atomicAdd(&g_deg[edge_at(ei, (long long)N_EDGES + i, is64)], 1.0f);
}
__global__ void k_dinv() {
    int i = blockIdx.x * blockDim.x + threadIdx.x;
    if (i < N_NODES) g_dinv[i] = rsqrtf(g_deg[i]);
}

// ---------------------------------------------------------------------------
// Fused MLP: g_h2 = dinv * ( relu(X@W1 + b1) @ W2 )
// K-packed FFMA2: acc pairs accumulate (even-k, odd-k) partial sums.
// Weights transposed to K-major in smem with XOR bank swizzle on k-chunks.
// ---------------------------------------------------------------------------
#define SW1_STRIDE 68    // 64 k + pad (floats); *4 bytes = 272, 16B-aligned
#define SW2_STRIDE 132   // 128 k + pad; *4 = 528, 16B-aligned
#define SX_STRIDE  68
#define SH_STRIDE  132

__global__ __launch_bounds__(256, 1) void k_mlp(
    const float* __restrict__ X,
    const float* __restrict__ W1, const float* __restrict__ b1,
    const float* __restrict__ W2)
{
    extern __shared__ float sm[];
    float* sW1t = sm;                          // [128 c][68]
    float* sW2t = sW1t + 128 * SW1_STRIDE;     // [64 c][132]
    float* sX   = sW2t + 64 * SW2_STRIDE;      // [64 n][68]
    float* sH   = sX + 64 * SX_STRIDE;         // [64 n][132]
    int tid = threadIdx.x;

    // transpose W1 [64k x 128c] -> sW1t[c][k], k-chunk swizzled by (c>>3)&7
    for (int i = tid; i < IN_C * HID; i += 256) {
        int k = i >> 7, c = i & 127;
        int kc = ((k >> 2) ^ ((c >> 3) & 7)) << 2;
        sW1t[c * SW1_STRIDE + kc + (k & 3)] = W1[i];
    }
    // transpose W2 [128k x 64c] -> sW2t[c][k], swizzled by (c>>2)&7
    for (int i = tid; i < HID * OUT_C; i += 256) {
        int k = i >> 6, c = i & 63;
        int kc = ((k >> 2) ^ ((c >> 2) & 7)) << 2;
        sW2t[c * SW2_STRIDE + kc + (k & 3)] = W2[i];
    }
    int c2 = tid & 15;     // column group
    int ng = tid >> 4;     // node group (4 nodes)
    float b1r[8];
    #pragma unroll
    for (int j = 0; j < 8; ++j) b1r[j] = b1[8 * c2 + j];
    __syncthreads();

    int sw1 = (c2 & 7) << 2;   // stage1 swizzle for this thread's cols (c>>3 == c2)
    for (int tile = blockIdx.x; tile < N_TILES; tile += gridDim.x) {
        int nbase = tile * 64;

        // load X tile [64 x 64] coalesced
        for (int q = tid; q < 1024; q += 256) {
            int n = q >> 4, t = q & 15;
            float4 v = make_float4(0.f, 0.f, 0.f, 0.f);
            if (nbase + n < N_NODES)
                v = ((const float4*)X)[(size_t)(nbase + n) * 16 + t];
            *(float4*)&sX[n * SX_STRIDE + t * 4] = v;
        }
        __syncthreads();

        // ---- stage 1: sH[64x128] = relu(X @ W1 + b1), thread: 4 nodes x 8 cols
        {
            u64 acc[4][8];
            #pragma unroll
            for (int i = 0; i < 4; ++i)
                #pragma unroll
                for (int j = 0; j < 8; ++j) acc[i][j] = 0ull;

            #pragma unroll 2
            for (int kb = 0; kb < IN_C; kb += 4) {
                ulonglong2 xa[4];
                #pragma unroll
                for (int i = 0; i < 4; ++i)
                    xa[i] = *(const ulonglong2*)&sX[(ng * 4 + i) * SX_STRIDE + kb];
                int kphys = (kb ^ sw1);
                #pragma unroll
                for (int j = 0; j < 8; ++j) {
                    ulonglong2 wv = *(const ulonglong2*)&sW1t[(8 * c2 + j) * SW1_STRIDE + kphys];
                    #pragma unroll
                    for (int i = 0; i < 4; ++i) {
                        acc[i][j] = ffma2(xa[i].x, wv.x, acc[i][j]);
                        acc[i][j] = ffma2(xa[i].y, wv.y, acc[i][j]);
                    }
                }
            }
            // fold + bias + relu -> sH (k-major for stage2)
            #pragma unroll
            for (int i = 0; i < 4; ++i) {
                int n = ng * 4 + i;
                #pragma unroll
                for (int jp = 0; jp < 4; ++jp) {
                    float l0, h0, l1, h1;
                    unpack2(acc[i][2 * jp],     l0, h0);
                    unpack2(acc[i][2 * jp + 1], l1, h1);
                    float v0 = fmaxf(l0 + h0 + b1r[2 * jp],     0.f);
                    float v1 = fmaxf(l1 + h1 + b1r[2 * jp + 1], 0.f);
                    *(u64*)&sH[n * SH_STRIDE + 8 * c2 + 2 * jp] = pack2(v0, v1);
                }
            }
        }
        __syncthreads();

        // ---- stage 2: h2[64x64] = sH @ W2, thread: 4 nodes x 4 cols
        {
            u64 o[4][4];
            #pragma unroll
            for (int i = 0; i < 4; ++i)
                #pragma unroll
                for (int j = 0; j < 4; ++j) o[i][j] = 0ull;

            #pragma unroll 2
            for (int kb = 0; kb < HID; kb += 4) {
                ulonglong2 ha[4];
                #pragma unroll
                for (int i = 0; i < 4; ++i)
                    ha[i] = *(const ulonglong2*)&sH[(ng * 4 + i) * SH_STRIDE + kb];
                #pragma unroll
                for (int j = 0; j < 4; ++j) {
                    int c = 4 * c2 + j;
                    int kphys = kb ^ (((c >> 2) & 7) << 2);
                    ulonglong2 wv = *(const ulonglong2*)&sW2t[c * SW2_STRIDE + kphys];
                    #pragma unroll
                    for (int i = 0; i < 4; ++i) {
                        o[i][j] = ffma2(ha[i].x, wv.x, o[i][j]);
                        o[i][j] = ffma2(ha[i].y, wv.y, o[i][j]);
                    }
                }
            }
            #pragma unroll
            for (int i = 0; i < 4; ++i) {
                int n = nbase + ng * 4 + i;
                if (n < N_NODES) {
                    float di = g_dinv[n];
                    float4 r;
                    float a, b;
                    unpack2(o[i][0], a, b); r.x = (a + b) * di;
                    unpack2(o[i][1], a, b); r.y = (a + b) * di;
                    unpack2(o[i][2], a, b); r.z = (a + b) * di;
                    unpack2(o[i][3], a, b); r.w = (a + b) * di;
                    ((float4*)g_h2)[(size_t)n * 16 + c2] = r;
                }
            }
        }
        __syncthreads();   // protect sX/sH before next tile
    }
}

// ---------------------------------------------------------------------------
// CSR offsets via scan of in-degrees
// ---------------------------------------------------------------------------
__global__ void k_scan1() {
    __shared__ int sh[512];
    int tid = threadIdx.x;
    int i = blockIdx.x * 512 + tid;
    int v = (i < N_NODES) ? ((int)g_deg[i] - 1) : 0;
    sh[tid] = v;
    __syncthreads();
    for (int off = 1; off < 512; off <<= 1) {
        int t = (tid >= off) ? sh[tid - off] : 0;
        __syncthreads();
        sh[tid] += t;
        __syncthreads();
    }
    if (i < N_NODES) { g_off[i] = sh[tid] - v; g_cursor[i] = 0; }
    if (tid == 511) g_bsum[blockIdx.x] = sh[511];
}
__global__ void k_scan2() {
    __shared__ int sh[256];
    int tid = threadIdx.x;
    int v = (tid < NB1) ? g_bsum[tid] : 0;
    sh[tid] = v;
    __syncthreads();
    for (int off = 1; off < 256; off <<= 1) {
        int t = (tid >= off) ? sh[tid - off] : 0;
        __syncthreads();
        sh[tid] += t;
        __syncthreads();
    }
    if (tid < NB1) g_bsum[tid] = sh[tid] - v;
}
__global__ void k_scan3() {
    int i = blockIdx.x * blockDim.x + threadIdx.x;
    if (i < N_NODES) g_off[i] += g_bsum[i >> 9];
}

// ---------------------------------------------------------------------------
// Bin edges by dst
// ---------------------------------------------------------------------------
__global__ void k_bin(const void* __restrict__ ei) {
    int is64 = g_is64;
    int stride = gridDim.x * blockDim.x;
    for (int e = blockIdx.x * blockDim.x + threadIdx.x; e < N_EDGES; e += stride) {
        int s = edge_at(ei, e, is64);
        int d = edge_at(ei, (long long)N_EDGES + e, is64);
        int pos = atomicAdd(&g_cursor[d], 1);
        g_esrc[g_off[d] + pos] = s;
    }
}

// ---------------------------------------------------------------------------
// Gather: warp per dst. g_h2 pre-scaled by dinv[src], so messages are pure
// adds. Half-warps process 2 edges concurrently with LDG.128.
// out[d] = b2 + dinv[d] * (sum_s h2hat[s] + h2hat[d])
// ---------------------------------------------------------------------------
__global__ __launch_bounds__(256) void k_gather(
    const float* __restrict__ b2, float* __restrict__ out)
{
    int lane = threadIdx.x & 31;
    int d = (blockIdx.x * blockDim.x + threadIdx.x) >> 5;
    if (d >= N_NODES) return;
    int half = lane >> 4, q = lane & 15;

    int cnt = (int)g_deg[d] - 1;
    int base = g_off[d];
    float4 acc = make_float4(0.f, 0.f, 0.f, 0.f);

    for (int c = 0; c < cnt; c += 32) {
        int m = cnt - c; if (m > 32) m = 32;
        int s = (lane < m) ? g_esrc[base + c + lane] : 0;
        int iters = (m + 1) >> 1;
        for (int t = 0; t < iters; ++t) {
            int idx = 2 * t + half;
            int sj = __shfl_sync(0xffffffffu, s, idx);
            if (idx < m) {
                float4 v = ((const float4*)g_h2)[(size_t)sj * 16 + q];
                acc.x += v.x; acc.y += v.y; acc.z += v.z; acc.w += v.w;
            }
        }
    }
    // combine the two half-warp partials
    acc.x += __shfl_down_sync(0xffffffffu, acc.x, 16);
    acc.y += __shfl_down_sync(0xffffffffu, acc.y, 16);
    acc.z += __shfl_down_sync(0xffffffffu, acc.z, 16);
    acc.w += __shfl_down_sync(0xffffffffu, acc.w, 16);

    if (half == 0) {
        float di = g_dinv[d];
        float4 hs = ((const float4*)g_h2)[(size_t)d * 16 + q];
        float4 bb = ((const float4*)b2)[q];
        float4 o;
        o.x = fmaf(di, acc.x + hs.x, bb.x);
        o.y = fmaf(di, acc.y + hs.y, bb.y);
        o.z = fmaf(di, acc.z + hs.z, bb.z);
        o.w = fmaf(di, acc.w + hs.w, bb.w);
        ((float4*)out)[(size_t)d * 16 + q] = o;
    }
}

// ---------------------------------------------------------------------------
// Launch. Inputs: X f32[N*64], edge_index (i32/i64)[2E], W1, b1, W2, b2.
// ---------------------------------------------------------------------------
extern "C" void kernel_launch(void* const* d_in, const int* in_sizes, int n_in,
                              void* d_out, int out_size)
{
    const float* X  = (const float*)d_in[0];
    const void*  EI = d_in[1];
    const float* W1 = (const float*)d_in[2];
    const float* b1 = (const float*)d_in[3];
    const float* W2 = (const float*)d_in[4];
    const float* b2 = (const float*)d_in[5];
    float* out = (float*)d_out;

    size_t smem = (size_t)(128 * SW1_STRIDE + 64 * SW2_STRIDE +
                           64 * SX_STRIDE + 64 * SH_STRIDE) * sizeof(float);
    cudaFuncSetAttribute(k_mlp, cudaFuncAttributeMaxDynamicSharedMemorySize, (int)smem);

    k_init<<<(N_NODES + 255) / 256, 256>>>((const int*)EI);   // 0
    k_deg_count<<<1184, 256>>>(EI);                           // 1
    k_dinv<<<(N_NODES + 255) / 256, 256>>>();                 // 2
    k_mlp<<<148, 256, smem>>>(X, W1, b1, W2);                 // 3  <- ncu aim
    k_scan1<<<NB1, 512>>>();                                  // 4
    k_scan2<<<1, 256>>>();                                    // 5
    k_scan3<<<(N_NODES + 255) / 256, 256>>>();                // 6
    k_bin<<<1184, 256>>>(EI);                                 // 7
    k_gather<<<(N_NODES * 32) / 256, 256>>>(b2, out);         // 8
}

// round 6
// speedup vs baseline: 2.4715x; 1.5425x over previous
#include <cuda_runtime.h>
#include <cuda_bf16.h>
#include <cstdint>

#define N_NODES 100000
#define N_EDGES 1600000
#define IN_C 64
#define HID 128
#define OUT_C 64
#define NB1 196              // ceil(N_NODES/512)
#define TILE_M 128
#define N_TILES 782          // ceil(N_NODES/128)

// Scratch (__device__ globals; no allocs allowed)
__device__ float g_h2[(size_t)N_NODES * OUT_C];   // dinv-scaled post-W2 features
__device__ float g_deg[N_NODES];
__device__ float g_dinv[N_NODES];
__device__ int   g_off[N_NODES];
__device__ int   g_cursor[N_NODES];
__device__ int   g_bsum[NB1];
__device__ int   g_esrc[N_EDGES];
__device__ int   g_is64;

// ---------------------------------------------------------------------------
// bf16 helpers
// ---------------------------------------------------------------------------
__device__ __forceinline__ void split2(float x, float y, uint32_t& hi, uint32_t& lo) {
    __nv_bfloat162 h = __floats2bfloat162_rn(x, y);
    float hx = __bfloat162float(h.x), hy = __bfloat162float(h.y);
    hi = *(uint32_t*)&h;
    __nv_bfloat162 l = __floats2bfloat162_rn(x - hx, y - hy);
    lo = *(uint32_t*)&l;
}

// D += A(16x16 bf16) @ B(16x8 bf16), fp32 accum
__device__ __forceinline__ void mma_bf16(float* d, const uint32_t* a,
                                         uint32_t b0, uint32_t b1) {
    asm("mma.sync.aligned.m16n8k16.row.col.f32.bf16.bf16.f32 "
        "{%0,%1,%2,%3}, {%4,%5,%6,%7}, {%8,%9}, {%0,%1,%2,%3};"
        : "+f"(d[0]), "+f"(d[1]), "+f"(d[2]), "+f"(d[3])
        : "r"(a[0]), "r"(a[1]), "r"(a[2]), "r"(a[3]), "r"(b0), "r"(b1));
}

// ---------------------------------------------------------------------------
// init: deg=1 (self-loop) + edge dtype detection
// ---------------------------------------------------------------------------
__global__ void k_init(const int* __restrict__ w) {
    int i = blockIdx.x * blockDim.x + threadIdx.x;
    if (i < N_NODES) g_deg[i] = 1.0f;
    if (i == 0) {
        int nz = 0;
        #pragma unroll 8
        for (int j = 0; j < 128; ++j) nz += (w[2 * j + 1] != 0);
        g_is64 = (nz == 0) ? 1 : 0;
    }
}
__device__ __forceinline__ int edge_at(const void* ei, long long i, int is64) {
    return is64 ? (int)((const long long*)ei)[i] : ((const int*)ei)[i];
}
__global__ void k_deg_count(const void* __restrict__ ei) {
    int is64 = g_is64;
    int stride = gridDim.x * blockDim.x;
    for (int i = blockIdx.x * blockDim.x + threadIdx.x; i < N_EDGES; i += stride)
        atomicAdd(&g_deg[edge_at(ei, (long long)N_EDGES + i, is64)], 1.0f);
}
__global__ void k_dinv() {
    int i = blockIdx.x * blockDim.x + threadIdx.x;
    if (i < N_NODES) g_dinv[i] = rsqrtf(g_deg[i]);
}

// ---------------------------------------------------------------------------
// Tensor-core MLP (mma.sync bf16, split-precision):
//   g_h2 = dinv * ( relu(X@W1 + b1) @ W2 )
// Tile = 128 nodes, 8 warps x m16. Hidden activations stay in registers:
// m16n8k16 C-fragment layout == next GEMM's A-fragment layout.
// SMEM fragment packs: A -> LDS.128, B -> LDS.64, all conflict-free.
// ---------------------------------------------------------------------------
#define NKS1 4    // stage1 k16 steps (K=64)
#define NNT1 16   // stage1 n8 tiles  (N=128)
#define NKS2 8    // stage2 k16 steps (K=128)
#define NNT2 8    // stage2 n8 tiles  (N=64)

// smem byte offsets
#define S_XA_HI 0          // 8 mb * 4 ks * 32 lanes * 16B = 16384
#define S_XA_LO 16384
#define S_W1_HI 32768      // 4 ks * 16 nt * 32 * 8B = 16384
#define S_W1_LO 49152
#define S_W2_HI 65536      // 8 ks * 8 nt * 32 * 8B = 16384
#define S_W2_LO 81920
#define S_B1    98304      // 128 f32
#define S_DINV  98816      // 128 f32
#define S_TOTAL 99328

__global__ __launch_bounds__(256) void k_mlp(
    const float* __restrict__ X,
    const float* __restrict__ W1, const float* __restrict__ b1,
    const float* __restrict__ W2)
{
    extern __shared__ char sm[];
    uint4* sXaH = (uint4*)(sm + S_XA_HI);
    uint4* sXaL = (uint4*)(sm + S_XA_LO);
    uint2* sW1H = (uint2*)(sm + S_W1_HI);
    uint2* sW1L = (uint2*)(sm + S_W1_LO);
    uint2* sW2H = (uint2*)(sm + S_W2_HI);
    uint2* sW2L = (uint2*)(sm + S_W2_LO);
    float* sB1  = (float*)(sm + S_B1);
    float* sDinv= (float*)(sm + S_DINV);

    int tid = threadIdx.x, wid = tid >> 5, lane = tid & 31;
    int g = lane >> 2, c = lane & 3;

    // ---- one-time: pack W1, W2 fragments (hi/lo split)
    for (int s = tid; s < NKS1 * NNT1 * 32; s += 256) {
        int ks = s >> 9, rem = s & 511, nt = rem >> 5, ln = rem & 31;
        int n = nt * 8 + (ln >> 2), k0 = ks * 16 + (ln & 3) * 2;
        float w00 = W1[(k0)     * HID + n], w01 = W1[(k0 + 1) * HID + n];
        float w10 = W1[(k0 + 8) * HID + n], w11 = W1[(k0 + 9) * HID + n];
        uint2 h, l;
        split2(w00, w01, h.x, l.x);
        split2(w10, w11, h.y, l.y);
        sW1H[s] = h; sW1L[s] = l;
    }
    for (int s = tid; s < NKS2 * NNT2 * 32; s += 256) {
        int ks = s >> 8, rem = s & 255, nt = rem >> 5, ln = rem & 31;
        int n = nt * 8 + (ln >> 2), k0 = ks * 16 + (ln & 3) * 2;
        float w00 = W2[(k0)     * OUT_C + n], w01 = W2[(k0 + 1) * OUT_C + n];
        float w10 = W2[(k0 + 8) * OUT_C + n], w11 = W2[(k0 + 9) * OUT_C + n];
        uint2 h, l;
        split2(w00, w01, h.x, l.x);
        split2(w10, w11, h.y, l.y);
        sW2H[s] = h; sW2L[s] = l;
    }
    if (tid < HID) sB1[tid] = b1[tid];
    __syncthreads();

    for (int tile = blockIdx.x; tile < N_TILES; tile += gridDim.x) {
        int nbase = tile * TILE_M;

        // per-tile dinv
        if (tid < TILE_M)
            sDinv[tid] = (nbase + tid < N_NODES) ? g_dinv[nbase + tid] : 0.f;

        // pack X tile into A fragments (hi/lo)
        #pragma unroll
        for (int it = 0; it < 4; ++it) {
            int s = tid + 256 * it;                   // 1024 slots
            int mb = s >> 7, ks = (s >> 5) & 3, ln = s & 31;
            int row = mb * 16 + (ln >> 2);
            int n0 = nbase + row, n8 = n0 + 8;
            int k0 = ks * 16 + (ln & 3) * 2;
            float2 z = make_float2(0.f, 0.f);
            float2 x00 = (n0 < N_NODES) ? *(const float2*)&X[(size_t)n0 * IN_C + k0]     : z;
            float2 x01 = (n0 < N_NODES) ? *(const float2*)&X[(size_t)n0 * IN_C + k0 + 8] : z;
            float2 x10 = (n8 < N_NODES) ? *(const float2*)&X[(size_t)n8 * IN_C + k0]     : z;
            float2 x11 = (n8 < N_NODES) ? *(const float2*)&X[(size_t)n8 * IN_C + k0 + 8] : z;
            uint4 h, l;
            split2(x00.x, x00.y, h.x, l.x);
            split2(x10.x, x10.y, h.y, l.y);
            split2(x01.x, x01.y, h.z, l.z);
            split2(x11.x, x11.y, h.w, l.w);
            sXaH[s] = h; sXaL[s] = l;
        }
        __syncthreads();

        // ---- stage 1: acc[16][4] = X @ W1  (3-pass split)
        float acc[NNT1][4];
        #pragma unroll
        for (int nt = 0; nt < NNT1; ++nt)
            #pragma unroll
            for (int q = 0; q < 4; ++q) acc[nt][q] = 0.f;

        #pragma unroll
        for (int ks = 0; ks < NKS1; ++ks) {
            uint4 ah = sXaH[(wid * NKS1 + ks) * 32 + lane];
            uint4 al = sXaL[(wid * NKS1 + ks) * 32 + lane];
            #pragma unroll
            for (int nt = 0; nt < NNT1; ++nt) {
                uint2 bh = sW1H[(ks * NNT1 + nt) * 32 + lane];
                uint2 bl = sW1L[(ks * NNT1 + nt) * 32 + lane];
                mma_bf16(acc[nt], (const uint32_t*)&ah, bh.x, bh.y);
                mma_bf16(acc[nt], (const uint32_t*)&ah, bl.x, bl.y);
                mma_bf16(acc[nt], (const uint32_t*)&al, bh.x, bh.y);
            }
        }

        // ---- bias + relu + split; repack in-register as stage-2 A fragments
        uint4 Hh[NKS2], Hl[NKS2];
        #pragma unroll
        for (int nt = 0; nt < NNT1; ++nt) {
            float2 bb = *(const float2*)&sB1[nt * 8 + c * 2];
            float v0 = fmaxf(acc[nt][0] + bb.x, 0.f);
            float v1 = fmaxf(acc[nt][1] + bb.y, 0.f);
            float v2 = fmaxf(acc[nt][2] + bb.x, 0.f);
            float v3 = fmaxf(acc[nt][3] + bb.y, 0.f);
            uint32_t h01, l01, h23, l23;
            split2(v0, v1, h01, l01);
            split2(v2, v3, h23, l23);
            int k2 = nt >> 1;
            if ((nt & 1) == 0) { Hh[k2].x = h01; Hh[k2].y = h23; Hl[k2].x = l01; Hl[k2].y = l23; }
            else               { Hh[k2].z = h01; Hh[k2].w = h23; Hl[k2].z = l01; Hl[k2].w = l23; }
        }

        // ---- stage 2: acc2[8][4] = H @ W2
        float acc2[NNT2][4];
        #pragma unroll
        for (int nt = 0; nt < NNT2; ++nt)
            #pragma unroll
            for (int q = 0; q < 4; ++q) acc2[nt][q] = 0.f;

        #pragma unroll
        for (int ks = 0; ks < NKS2; ++ks) {
            #pragma unroll
            for (int nt = 0; nt < NNT2; ++nt) {
                uint2 bh = sW2H[(ks * NNT2 + nt) * 32 + lane];
                uint2 bl = sW2L[(ks * NNT2 + nt) * 32 + lane];
                mma_bf16(acc2[nt], (const uint32_t*)&Hh[ks], bh.x, bh.y);
                mma_bf16(acc2[nt], (const uint32_t*)&Hh[ks], bl.x, bl.y);
                mma_bf16(acc2[nt], (const uint32_t*)&Hl[ks], bh.x, bh.y);
            }
        }

        // ---- epilogue: scale by dinv, write g_h2
        {
            int r0 = wid * 16 + g;
            int node0 = nbase + r0, node8 = node0 + 8;
            float d0 = sDinv[r0], d8 = sDinv[r0 + 8];
            #pragma unroll
            for (int nt = 0; nt < NNT2; ++nt) {
                int n0 = nt * 8 + c * 2;
                if (node0 < N_NODES)
                    *(float2*)&g_h2[(size_t)node0 * OUT_C + n0] =
                        make_float2(acc2[nt][0] * d0, acc2[nt][1] * d0);
                if (node8 < N_NODES)
                    *(float2*)&g_h2[(size_t)node8 * OUT_C + n0] =
                        make_float2(acc2[nt][2] * d8, acc2[nt][3] * d8);
            }
        }
        __syncthreads();   // sXa reuse next tile
    }
}

// ---------------------------------------------------------------------------
// CSR offsets via scan of in-degrees
// ---------------------------------------------------------------------------
__global__ void k_scan1() {
    __shared__ int sh[512];
    int tid = threadIdx.x;
    int i = blockIdx.x * 512 + tid;
    int v = (i < N_NODES) ? ((int)g_deg[i] - 1) : 0;
    sh[tid] = v;
    __syncthreads();
    for (int off = 1; off < 512; off <<= 1) {
        int t = (tid >= off) ? sh[tid - off] : 0;
        __syncthreads();
        sh[tid] += t;
        __syncthreads();
    }
    if (i < N_NODES) { g_off[i] = sh[tid] - v; g_cursor[i] = 0; }
    if (tid == 511) g_bsum[blockIdx.x] = sh[511];
}
__global__ void k_scan2() {
    __shared__ int sh[256];
    int tid = threadIdx.x;
    int v = (tid < NB1) ? g_bsum[tid] : 0;
    sh[tid] = v;
    __syncthreads();
    for (int off = 1; off < 256; off <<= 1) {
        int t = (tid >= off) ? sh[tid - off] : 0;
        __syncthreads();
        sh[tid] += t;
        __syncthreads();
    }
    if (tid < NB1) g_bsum[tid] = sh[tid] - v;
}
__global__ void k_scan3() {
    int i = blockIdx.x * blockDim.x + threadIdx.x;
    if (i < N_NODES) g_off[i] += g_bsum[i >> 9];
}

// ---------------------------------------------------------------------------
// Bin edges by dst
// ---------------------------------------------------------------------------
__global__ void k_bin(const void* __restrict__ ei) {
    int is64 = g_is64;
    int stride = gridDim.x * blockDim.x;
    for (int e = blockIdx.x * blockDim.x + threadIdx.x; e < N_EDGES; e += stride) {
        int s = edge_at(ei, e, is64);
        int d = edge_at(ei, (long long)N_EDGES + e, is64);
        int pos = atomicAdd(&g_cursor[d], 1);
        g_esrc[g_off[d] + pos] = s;
    }
}

// ---------------------------------------------------------------------------
// Gather: warp per dst, h2 pre-scaled by dinv[src] -> pure adds.
// out[d] = b2 + dinv[d] * (sum_s h2hat[s] + h2hat[d])
// ---------------------------------------------------------------------------
__global__ __launch_bounds__(256) void k_gather(
    const float* __restrict__ b2, float* __restrict__ out)
{
    int lane = threadIdx.x & 31;
    int d = (blockIdx.x * blockDim.x + threadIdx.x) >> 5;
    if (d >= N_NODES) return;
    int half = lane >> 4, q = lane & 15;

    int cnt = (int)g_deg[d] - 1;
    int base = g_off[d];
    float4 acc = make_float4(0.f, 0.f, 0.f, 0.f);

    for (int cbase = 0; cbase < cnt; cbase += 32) {
        int m = cnt - cbase; if (m > 32) m = 32;
        int s = (lane < m) ? g_esrc[base + cbase + lane] : 0;
        int iters = (m + 1) >> 1;
        for (int t = 0; t < iters; ++t) {
            int idx = 2 * t + half;
            int sj = __shfl_sync(0xffffffffu, s, idx);
            if (idx < m) {
                float4 v = ((const float4*)g_h2)[(size_t)sj * 16 + q];
                acc.x += v.x; acc.y += v.y; acc.z += v.z; acc.w += v.w;
            }
        }
    }
    acc.x += __shfl_down_sync(0xffffffffu, acc.x, 16);
    acc.y += __shfl_down_sync(0xffffffffu, acc.y, 16);
    acc.z += __shfl_down_sync(0xffffffffu, acc.z, 16);
    acc.w += __shfl_down_sync(0xffffffffu, acc.w, 16);

    if (half == 0) {
        float di = g_dinv[d];
        float4 hs = ((const float4*)g_h2)[(size_t)d * 16 + q];
        float4 bb = ((const float4*)b2)[q];
        float4 o;
        o.x = fmaf(di, acc.x + hs.x, bb.x);
        o.y = fmaf(di, acc.y + hs.y, bb.y);
        o.z = fmaf(di, acc.z + hs.z, bb.z);
        o.w = fmaf(di, acc.w + hs.w, bb.w);
        ((float4*)out)[(size_t)d * 16 + q] = o;
    }
}

// ---------------------------------------------------------------------------
// Launch. Inputs: X f32[N*64], edge_index (i32/i64)[2E], W1, b1, W2, b2.
// ---------------------------------------------------------------------------
extern "C" void kernel_launch(void* const* d_in, const int* in_sizes, int n_in,
                              void* d_out, int out_size)
{
    const float* X  = (const float*)d_in[0];
    const void*  EI = d_in[1];
    const float* W1 = (const float*)d_in[2];
    const float* b1 = (const float*)d_in[3];
    const float* W2 = (const float*)d_in[4];
    const float* b2 = (const float*)d_in[5];
    float* out = (float*)d_out;

    cudaFuncSetAttribute(k_mlp, cudaFuncAttributeMaxDynamicSharedMemorySize, S_TOTAL);

    k_init<<<(N_NODES + 255) / 256, 256>>>((const int*)EI);   // 0
    k_deg_count<<<1184, 256>>>(EI);                           // 1
    k_dinv<<<(N_NODES + 255) / 256, 256>>>();                 // 2
    k_mlp<<<296, 256, S_TOTAL>>>(X, W1, b1, W2);              // 3  <- ncu aim
    k_scan1<<<NB1, 512>>>();                                  // 4
    k_scan2<<<1, 256>>>();                                    // 5
    k_scan3<<<(N_NODES + 255) / 256, 256>>>();                // 6
    k_bin<<<1184, 256>>>(EI);                                 // 7
    k_gather<<<(N_NODES * 32) / 256, 256>>>(b2, out);         // 8
}